// round 6
// baseline (speedup 1.0000x reference)
#include <cuda_runtime.h>
#include <cuda_bf16.h>

// ht[b,d] = sum_{s=start}^{start+x-1} hidden[b,s,d]
// start = sum(mask[B-1, :]) - x   (JAX x64-disabled: mask & x are int32)
//
// Fast path (one barrier): speculatively load rows [S-64, S) (addresses are
// load-independent), concurrently check "x==64 and every mask[B-1,i]==1"
// (=> start == S-64) with a pure bitwise predicate. Partial sums go to smem
// BEFORE the single __syncthreads_and, which both synchronizes and reduces
// the predicate. Slow path (block-uniform branch) recomputes generically for
// any mask/x. No cross-block communication.

__global__ void __launch_bounds__(256)
srsmlp_window_sum_kernel(const float* __restrict__ hidden,
                         const int* __restrict__ mask,
                         const int* __restrict__ xptr,
                         float* __restrict__ out,
                         int B, int S, int D4, int chunks /* D4/16 */)
{
    const int tid = threadIdx.x;
    const int col = tid & 15;         // float4 column within 16-wide chunk
    const int sg  = tid >> 4;         // s-group 0..15
    const int b     = blockIdx.x / chunks;
    const int chunk = blockIdx.x - b * chunks;

    const int d4 = (chunk << 4) + col;
    const float4* __restrict__ hid4 = reinterpret_cast<const float4*>(hidden);
    float4* __restrict__ out4 = reinterpret_cast<float4*>(out);

    // ---- speculative window loads: rows [S-64, S), no load dependencies ----
    const bool can_spec = (S >= 64);
    const int  gs = S - 64;
    const float4* __restrict__ sbase =
        hid4 + ((long long)b * S + gs) * D4 + d4;
    float4 v0, v1, v2, v3;
    if (can_spec) {
        v0 = sbase[(long long)(sg)      * D4];
        v1 = sbase[(long long)(sg + 16) * D4];
        v2 = sbase[(long long)(sg + 32) * D4];
        v3 = sbase[(long long)(sg + 48) * D4];
    } else {
        v0 = v1 = v2 = v3 = make_float4(0.f,0.f,0.f,0.f);
    }

    // ---- concurrent scalar + mask predicate loads ----
    const int x = __ldg(xptr);
    const int* mrow = mask + (long long)(B - 1) * S;
    const int  S4   = S >> 2;
    const int4* mrow4 = reinterpret_cast<const int4*>(mrow);

    int okbits = (x == 64) & (int)can_spec;
    for (int i = tid; i < S4; i += 256) {           // 2 int4 loads for S=2048
        int4 m = mrow4[i];
        okbits &= (m.x == 1) & (m.y == 1) & (m.z == 1) & (m.w == 1);
    }
    for (int i = (S4 << 2) + tid; i < S; i += 256)
        okbits &= (mrow[i] == 1);

    // ---- combine speculative partials, stage in smem (pre-barrier) ----
    float4 a;
    a.x = (v0.x + v1.x) + (v2.x + v3.x);
    a.y = (v0.y + v1.y) + (v2.y + v3.y);
    a.z = (v0.z + v1.z) + (v2.z + v3.z);
    a.w = (v0.w + v1.w) + (v2.w + v3.w);

    __shared__ float4 red[16][16];    // 4 KB
    red[sg][col] = a;

    // ---- single barrier: sync + block-wide AND of the predicate ----
    const int allok = __syncthreads_and(okbits);

    if (allok) {
        if (tid < 16) {
            float4 t = red[0][tid];
            #pragma unroll
            for (int j = 1; j < 16; ++j) {
                float4 v = red[j][tid];
                t.x += v.x; t.y += v.y; t.z += v.z; t.w += v.w;
            }
            out4[(long long)b * D4 + (chunk << 4) + tid] = t;
        }
        return;
    }

    // ================= slow path (any mask / any x; block-uniform) =========
    __shared__ int s_len;
    if (tid == 0) s_len = 0;
    __syncthreads();
    {
        int macc = 0;
        for (int i = tid; i < S4; i += 256) {
            int4 m = mrow4[i];
            macc += m.x + m.y + m.z + m.w;
        }
        for (int i = (S4 << 2) + tid; i < S; i += 256)
            macc += mrow[i];
        #pragma unroll
        for (int off = 16; off > 0; off >>= 1)
            macc += __shfl_down_sync(0xFFFFFFFFu, macc, off);
        if ((tid & 31) == 0)
            atomicAdd(&s_len, macc);
    }
    __syncthreads();

    const int start = s_len - x;
    float4 acc = make_float4(0.f,0.f,0.f,0.f);
    const float4* __restrict__ tbase =
        hid4 + ((long long)b * S + start) * D4 + d4;
    for (int r = sg; r < x; r += 16) {
        float4 v = tbase[(long long)r * D4];
        acc.x += v.x; acc.y += v.y; acc.z += v.z; acc.w += v.w;
    }

    __syncthreads();                  // red[] reuse
    red[sg][col] = acc;
    __syncthreads();

    if (tid < 16) {
        float4 t = red[0][tid];
        #pragma unroll
        for (int j = 1; j < 16; ++j) {
            float4 v = red[j][tid];
            t.x += v.x; t.y += v.y; t.z += v.z; t.w += v.w;
        }
        out4[(long long)b * D4 + (chunk << 4) + tid] = t;
    }
}

extern "C" void kernel_launch(void* const* d_in, const int* in_sizes, int n_in,
                              void* d_out, int out_size)
{
    const float* hidden = (const float*)d_in[0];
    const int*   mask   = (const int*)d_in[1];
    const int*   xptr   = (const int*)d_in[2];
    float*       out    = (float*)d_out;

    const long long hidden_elems = in_sizes[0];
    const long long mask_elems   = in_sizes[1];

    const int D  = (int)(hidden_elems / mask_elems);  // 1024
    const int B  = out_size / D;                      // 32
    const int S  = (int)(mask_elems / B);             // 2048
    const int D4 = D >> 2;                            // 256
    const int chunks = D4 >> 4;                       // 16

    dim3 grid(B * chunks);                            // 512 blocks
    srsmlp_window_sum_kernel<<<grid, 256>>>(hidden, mask, xptr, out,
                                            B, S, D4, chunks);
}

// round 7
// speedup vs baseline: 1.0370x; 1.0370x over previous
#include <cuda_runtime.h>
#include <cuda_bf16.h>

// ht[b,d] = sum_{s=start}^{start+x-1} hidden[b,s,d]
// start = sum(mask[B-1, :]) - x   (JAX x64-disabled: mask & x are int32)
//
// Fast path (one barrier, minimal instructions):
//   - speculative window loads rows [S-64, S)  (load-independent addresses)
//   - predicate "x==64 && every mask[B-1,i]==1" via u64 pattern compares
//   - warp-shfl merges the two s-groups sharing each warp (no smem for that
//     stage), 8 warp-partials land in smem, single __syncthreads_and both
//     syncs and reduces the predicate, 16 threads finish.
// Slow path: generic (any mask / any x), block-uniform branch.

__global__ void __launch_bounds__(256)
srsmlp_window_sum_kernel(const float* __restrict__ hidden,
                         const int* __restrict__ mask,
                         const int* __restrict__ xptr,
                         float* __restrict__ out,
                         int B, int S, int D4, int chunks /* D4/16 */)
{
    const int tid  = threadIdx.x;
    const int col  = tid & 15;        // float4 column within 16-wide chunk
    const int sg   = tid >> 4;        // s-group 0..15
    const int lane = tid & 31;
    const int wid  = tid >> 5;        // warp 0..7 (covers sgs 2w, 2w+1)
    const int b     = blockIdx.x / chunks;
    const int chunk = blockIdx.x - b * chunks;

    const int d4 = (chunk << 4) + col;
    const unsigned rowB = (unsigned)(D4 << 4);        // row stride in bytes

    // ---- speculative window loads: rows [max(S-64,0), ...), no deps ----
    const bool can_spec = (S >= 64);
    const int  gs = can_spec ? (S - 64) : 0;
    const char* sbase = (const char*)hidden
        + ((long long)b * S + gs) * rowB + ((unsigned)d4 << 4);

    float4 v0 = *(const float4*)(sbase + (unsigned)(sg)      * rowB);
    float4 v1 = *(const float4*)(sbase + (unsigned)(sg + 16) * rowB);
    float4 v2 = *(const float4*)(sbase + (unsigned)(sg + 32) * rowB);
    float4 v3 = *(const float4*)(sbase + (unsigned)(sg + 48) * rowB);

    // ---- concurrent scalar + mask predicate loads ----
    const int x = __ldg(xptr);
    const int* mrow = mask + (long long)(B - 1) * S;
    const int  S4   = S >> 2;                       // 16B chunks
    const ulonglong2* m2 = reinterpret_cast<const ulonglong2*>(mrow);
    const unsigned long long ONES = 0x0000000100000001ULL;

    int okbits = (x == 64) & (int)can_spec & (int)((S & 3) == 0);
    if (S4 == 512) {                  // common case: straight-line, 2 loads
        ulonglong2 a = m2[tid];
        ulonglong2 c = m2[tid + 256];
        okbits &= (a.x == ONES) & (a.y == ONES) & (c.x == ONES) & (c.y == ONES);
    } else if ((S & 3) == 0) {
        for (int i = tid; i < S4; i += 256) {
            ulonglong2 m = m2[i];
            okbits &= (m.x == ONES) & (m.y == ONES);
        }
    }

    // ---- combine speculative partials ----
    float4 a;
    a.x = (v0.x + v1.x) + (v2.x + v3.x);
    a.y = (v0.y + v1.y) + (v2.y + v3.y);
    a.z = (v0.z + v1.z) + (v2.z + v3.z);
    a.w = (v0.w + v1.w) + (v2.w + v3.w);

    // ---- stage 1: merge the two s-groups within each warp via shfl ----
    a.x += __shfl_down_sync(0xFFFFFFFFu, a.x, 16);
    a.y += __shfl_down_sync(0xFFFFFFFFu, a.y, 16);
    a.z += __shfl_down_sync(0xFFFFFFFFu, a.z, 16);
    a.w += __shfl_down_sync(0xFFFFFFFFu, a.w, 16);

    __shared__ float4 red[8][16];     // 2 KB: 8 warp-partials x 16 cols
    if (lane < 16)
        red[wid][col] = a;

    // ---- single barrier: sync + block-wide AND of predicate ----
    const int allok = __syncthreads_and(okbits);

    float4* __restrict__ out4 = reinterpret_cast<float4*>(out);

    if (allok) {
        if (tid < 16) {
            float4 t = red[0][tid];
            #pragma unroll
            for (int j = 1; j < 8; ++j) {
                float4 v = red[j][tid];
                t.x += v.x; t.y += v.y; t.z += v.z; t.w += v.w;
            }
            out4[(long long)b * D4 + (chunk << 4) + tid] = t;
        }
        return;
    }

    // ================= slow path (any mask / any x; block-uniform) =========
    __shared__ int s_len;
    if (tid == 0) s_len = 0;
    __syncthreads();
    {
        int macc = 0;
        for (int i = tid; i < S4; i += 256) {
            int4 m = reinterpret_cast<const int4*>(mrow)[i];
            macc += m.x + m.y + m.z + m.w;
        }
        for (int i = (S4 << 2) + tid; i < S; i += 256)
            macc += mrow[i];
        #pragma unroll
        for (int off = 16; off > 0; off >>= 1)
            macc += __shfl_down_sync(0xFFFFFFFFu, macc, off);
        if ((tid & 31) == 0)
            atomicAdd(&s_len, macc);
    }
    __syncthreads();

    const int start = s_len - x;
    float4 acc = make_float4(0.f,0.f,0.f,0.f);
    const char* tbase = (const char*)hidden
        + ((long long)b * S + start) * rowB + ((unsigned)d4 << 4);
    for (int r = sg; r < x; r += 16) {
        float4 v = *(const float4*)(tbase + (unsigned)r * rowB);
        acc.x += v.x; acc.y += v.y; acc.z += v.z; acc.w += v.w;
    }

    acc.x += __shfl_down_sync(0xFFFFFFFFu, acc.x, 16);
    acc.y += __shfl_down_sync(0xFFFFFFFFu, acc.y, 16);
    acc.z += __shfl_down_sync(0xFFFFFFFFu, acc.z, 16);
    acc.w += __shfl_down_sync(0xFFFFFFFFu, acc.w, 16);

    __syncthreads();                  // red[] reuse
    if (lane < 16)
        red[wid][col] = acc;
    __syncthreads();

    if (tid < 16) {
        float4 t = red[0][tid];
        #pragma unroll
        for (int j = 1; j < 8; ++j) {
            float4 v = red[j][tid];
            t.x += v.x; t.y += v.y; t.z += v.z; t.w += v.w;
        }
        out4[(long long)b * D4 + (chunk << 4) + tid] = t;
    }
}

extern "C" void kernel_launch(void* const* d_in, const int* in_sizes, int n_in,
                              void* d_out, int out_size)
{
    const float* hidden = (const float*)d_in[0];
    const int*   mask   = (const int*)d_in[1];
    const int*   xptr   = (const int*)d_in[2];
    float*       out    = (float*)d_out;

    const long long hidden_elems = in_sizes[0];
    const long long mask_elems   = in_sizes[1];

    const int D  = (int)(hidden_elems / mask_elems);  // 1024
    const int B  = out_size / D;                      // 32
    const int S  = (int)(mask_elems / B);             // 2048
    const int D4 = D >> 2;                            // 256
    const int chunks = D4 >> 4;                       // 16

    dim3 grid(B * chunks);                            // 512 blocks
    srsmlp_window_sum_kernel<<<grid, 256>>>(hidden, mask, xptr, out,
                                            B, S, D4, chunks);
}

// round 8
// speedup vs baseline: 1.0821x; 1.0435x over previous
#include <cuda_runtime.h>
#include <cuda_bf16.h>

// ht[b,d] = sum_{s=start}^{start+x-1} hidden[b,s,d]
// start = sum(mask[B-1, :]) - x   (JAX x64-disabled: mask & x are int32)
//
// Fast path (one barrier): speculative window loads rows [S-64, S)
// (load-independent addresses), predicate "x==64 && all mask[B-1,i]==1"
// via one 16B u64x2 pattern-compare per thread, partials staged in smem
// BEFORE the single __syncthreads_and (sync + predicate reduce in one op),
// then warp 0 finishes. Slow path: generic (any mask / any x).
//
// Geometry: grid = B * (D4/32) = 256 blocks, 512 threads = 32 float4-cols
// x 16 s-groups. Each warp is one fully-coalesced 512B row slice.

__global__ void __launch_bounds__(512)
srsmlp_window_sum_kernel(const float* __restrict__ hidden,
                         const int* __restrict__ mask,
                         const int* __restrict__ xptr,
                         float* __restrict__ out,
                         int B, int S, int D4, int chunks /* D4/32 */)
{
    const int tid = threadIdx.x;
    const int col = tid & 31;         // float4 column within 32-wide chunk
    const int sg  = tid >> 5;         // s-group 0..15
    const int b     = blockIdx.x / chunks;
    const int chunk = blockIdx.x - b * chunks;

    const int d4 = (chunk << 5) + col;
    const unsigned rowB = (unsigned)(D4 << 4);        // row stride in bytes

    // ---- speculative window loads: rows [max(S-64,0), ...), no deps ----
    const bool can_spec = (S >= 64);
    const int  gs = can_spec ? (S - 64) : 0;
    const char* sbase = (const char*)hidden
        + ((long long)b * S + gs) * rowB + ((unsigned)d4 << 4);

    float4 v0 = *(const float4*)(sbase + (unsigned)(sg)      * rowB);
    float4 v1 = *(const float4*)(sbase + (unsigned)(sg + 16) * rowB);
    float4 v2 = *(const float4*)(sbase + (unsigned)(sg + 32) * rowB);
    float4 v3 = *(const float4*)(sbase + (unsigned)(sg + 48) * rowB);

    // ---- concurrent scalar + mask predicate (ONE 16B load per thread) ----
    const int x = __ldg(xptr);
    const int* mrow = mask + (long long)(B - 1) * S;
    const int  S4   = S >> 2;                       // 16B chunks
    const ulonglong2* m2 = reinterpret_cast<const ulonglong2*>(mrow);
    const unsigned long long ONES = 0x0000000100000001ULL;

    int okbits = (x == 64) & (int)can_spec & (int)((S & 3) == 0);
    if (S4 == 512) {                  // common case: exactly 1 load/thread
        ulonglong2 m = m2[tid];
        okbits &= (m.x == ONES) & (m.y == ONES);
    } else if ((S & 3) == 0) {
        for (int i = tid; i < S4; i += 512) {
            ulonglong2 m = m2[i];
            okbits &= (m.x == ONES) & (m.y == ONES);
        }
    }

    // ---- combine speculative partials, stage in smem (pre-barrier) ----
    float4 a;
    a.x = (v0.x + v1.x) + (v2.x + v3.x);
    a.y = (v0.y + v1.y) + (v2.y + v3.y);
    a.z = (v0.z + v1.z) + (v2.z + v3.z);
    a.w = (v0.w + v1.w) + (v2.w + v3.w);

    __shared__ float4 red[16][32];    // 8 KB: 16 s-group partials x 32 cols
    red[sg][col] = a;

    // ---- single barrier: sync + block-wide AND of predicate ----
    const int allok = __syncthreads_and(okbits);

    float4* __restrict__ out4 = reinterpret_cast<float4*>(out);

    if (allok) {
        if (tid < 32) {               // warp 0 finishes
            float4 t = red[0][tid];
            #pragma unroll
            for (int j = 1; j < 16; ++j) {
                float4 v = red[j][tid];
                t.x += v.x; t.y += v.y; t.z += v.z; t.w += v.w;
            }
            out4[(long long)b * D4 + (chunk << 5) + tid] = t;
        }
        return;
    }

    // ================= slow path (any mask / any x; block-uniform) =========
    __shared__ int s_len;
    if (tid == 0) s_len = 0;
    __syncthreads();
    {
        int macc = 0;
        for (int i = tid; i < S4; i += 512) {
            int4 m = reinterpret_cast<const int4*>(mrow)[i];
            macc += m.x + m.y + m.z + m.w;
        }
        for (int i = (S4 << 2) + tid; i < S; i += 512)
            macc += mrow[i];
        #pragma unroll
        for (int off = 16; off > 0; off >>= 1)
            macc += __shfl_down_sync(0xFFFFFFFFu, macc, off);
        if ((tid & 31) == 0)
            atomicAdd(&s_len, macc);
    }
    __syncthreads();

    const int start = s_len - x;
    float4 acc = make_float4(0.f,0.f,0.f,0.f);
    const char* tbase = (const char*)hidden
        + ((long long)b * S + start) * rowB + ((unsigned)d4 << 4);
    for (int r = sg; r < x; r += 16) {
        float4 v = *(const float4*)(tbase + (unsigned)r * rowB);
        acc.x += v.x; acc.y += v.y; acc.z += v.z; acc.w += v.w;
    }

    __syncthreads();                  // red[] reuse
    red[sg][col] = acc;
    __syncthreads();

    if (tid < 32) {
        float4 t = red[0][tid];
        #pragma unroll
        for (int j = 1; j < 16; ++j) {
            float4 v = red[j][tid];
            t.x += v.x; t.y += v.y; t.z += v.z; t.w += v.w;
        }
        out4[(long long)b * D4 + (chunk << 5) + tid] = t;
    }
}

extern "C" void kernel_launch(void* const* d_in, const int* in_sizes, int n_in,
                              void* d_out, int out_size)
{
    const float* hidden = (const float*)d_in[0];
    const int*   mask   = (const int*)d_in[1];
    const int*   xptr   = (const int*)d_in[2];
    float*       out    = (float*)d_out;

    const long long hidden_elems = in_sizes[0];
    const long long mask_elems   = in_sizes[1];

    const int D  = (int)(hidden_elems / mask_elems);  // 1024
    const int B  = out_size / D;                      // 32
    const int S  = (int)(mask_elems / B);             // 2048
    const int D4 = D >> 2;                            // 256
    const int chunks = D4 >> 5;                       // 8 (32 float4-cols/block)

    dim3 grid(B * chunks);                            // 256 blocks
    srsmlp_window_sum_kernel<<<grid, 512>>>(hidden, mask, xptr, out,
                                            B, S, D4, chunks);
}